// round 7
// baseline (speedup 1.0000x reference)
#include <cuda_runtime.h>
#include <cuda_bf16.h>

// out[o, b] = sum_k W[k, o] * X[b, k]
//   M = SIZE_OUT (o) = 2048, N = BATCH (b) = 8192, K = SIZE_IN = 2048
//   W row-major [SIZE_IN, SIZE_OUT]  -> A[o,k] = W[k*SIZE_OUT + o] (o contiguous)
//   X row-major [BATCH, SIZE_IN]     -> B[k,b] = X[b*SIZE_IN + k]  (k contiguous)
//   out row-major [SIZE_OUT, BATCH]: out[o*BATCH + b]
// Bias is intentionally NOT added (reference discards it).

#define BATCH_SZ 8192
#define SIZE_IN  2048
#define SIZE_OUT 2048

constexpr int BM = 128;   // o tile
constexpr int BN = 128;   // b tile
constexpr int BK = 16;    // k tile
constexpr int TM = 8;     // per-thread o
constexpr int TN = 8;     // per-thread b

__global__ __launch_bounds__(256, 2)
void sgemm_wt_xt_kernel(const float* __restrict__ X,   // [BATCH, SIZE_IN]
                        const float* __restrict__ W,   // [SIZE_IN, SIZE_OUT]
                        float* __restrict__ out)       // [SIZE_OUT, BATCH]
{
    __shared__ float As[BK][BM];   // As[k][o]
    __shared__ float Bs[BK][BN];   // Bs[k][b]

    const int t  = threadIdx.x;
    const int tx = t & 15;         // b sub-tile index
    const int ty = t >> 4;         // o sub-tile index

    const int oBase = blockIdx.y * BM;
    const int bBase = blockIdx.x * BN;

    // --- Global->reg staging maps ---
    // A tile (from W): BK rows(k) x BM cols(o) = 512 float4; 2 per thread.
    //   thread: k-row = t>>5 (and +8), o-col = (t&31)*4  -> fully coalesced.
    const int a_row = t >> 5;          // 0..7
    const int a_col = (t & 31) * 4;    // 0..124

    // B tile (from X): 128 b x 16 k. t<128: b=t, k-chunks 0..7; t>=128: b=t-128, k 8..15.
    //   Global: warp reads 32 rows x 16B (sector-aligned).
    //   Smem transposed store Bs[k][b]: per warp all lanes share k, b spans 32 banks
    //   -> conflict-free.
    const int b_b = t & 127;
    const int b_k = (t >> 7) * 8;      // 0 or 8

    const float* Wp = W + oBase + a_col;                 // + (kt + a_row)*SIZE_OUT
    const float* Xp = X + (bBase + b_b) * SIZE_IN + b_k; // + kt

    float4 a_ld0, a_ld1, b_ld0, b_ld1;
    float acc[TM][TN];
    #pragma unroll
    for (int i = 0; i < TM; i++)
        #pragma unroll
        for (int j = 0; j < TN; j++) acc[i][j] = 0.0f;

    // Prologue: stage tile kt=0
    a_ld0 = *(const float4*)(Wp + (0 + a_row) * SIZE_OUT);
    a_ld1 = *(const float4*)(Wp + (8 + a_row) * SIZE_OUT);
    b_ld0 = *(const float4*)(Xp + 0);
    b_ld1 = *(const float4*)(Xp + 4);

    for (int kt = 0; kt < SIZE_IN; kt += BK) {
        // regs -> smem
        *(float4*)&As[a_row][a_col]     = a_ld0;
        *(float4*)&As[a_row + 8][a_col] = a_ld1;
        {
            const float* p0 = (const float*)&b_ld0;
            const float* p1 = (const float*)&b_ld1;
            #pragma unroll
            for (int j = 0; j < 4; j++) {
                Bs[b_k + j][b_b]     = p0[j];
                Bs[b_k + 4 + j][b_b] = p1[j];
            }
        }
        __syncthreads();

        // Prefetch next tile (overlaps with compute below)
        if (kt + BK < SIZE_IN) {
            a_ld0 = *(const float4*)(Wp + (kt + BK + a_row) * SIZE_OUT);
            a_ld1 = *(const float4*)(Wp + (kt + BK + 8 + a_row) * SIZE_OUT);
            b_ld0 = *(const float4*)(Xp + kt + BK);
            b_ld1 = *(const float4*)(Xp + kt + BK + 4);
        }

        // Compute: 16 k-steps x 64 FFMA
        #pragma unroll
        for (int kk = 0; kk < BK; kk++) {
            float af[TM], bf[TN];
            *(float4*)&af[0] = *(const float4*)&As[kk][ty * 4];        // broadcast
            *(float4*)&af[4] = *(const float4*)&As[kk][64 + ty * 4];
            *(float4*)&bf[0] = *(const float4*)&Bs[kk][tx * 4];        // 16B x 16 lanes, c-free
            *(float4*)&bf[4] = *(const float4*)&Bs[kk][64 + tx * 4];
            #pragma unroll
            for (int i = 0; i < TM; i++)
                #pragma unroll
                for (int j = 0; j < TN; j++)
                    acc[i][j] = fmaf(af[i], bf[j], acc[i][j]);
        }
        __syncthreads();  // protect smem before next store
    }

    // Epilogue: out[o*BATCH + b], float4 along b, coalesced across tx
    #pragma unroll
    for (int i = 0; i < TM; i++) {
        const int o = oBase + ((i < 4) ? (ty * 4 + i) : (64 + ty * 4 + (i - 4)));
        float4 v0 = make_float4(acc[i][0], acc[i][1], acc[i][2], acc[i][3]);
        float4 v1 = make_float4(acc[i][4], acc[i][5], acc[i][6], acc[i][7]);
        *(float4*)&out[o * BATCH_SZ + bBase + tx * 4]      = v0;
        *(float4*)&out[o * BATCH_SZ + bBase + 64 + tx * 4] = v1;
    }
}

extern "C" void kernel_launch(void* const* d_in, const int* in_sizes, int n_in,
                              void* d_out, int out_size)
{
    // metadata order: in_values [8192,2048] f32, weights [2048,2048] f32, bias [2048] f32 (unused)
    const float* X = (const float*)d_in[0];
    const float* W = (const float*)d_in[1];
    float* out = (float*)d_out;

    dim3 grid(BATCH_SZ / BN, SIZE_OUT / BM);  // (64, 16)
    sgemm_wt_xt_kernel<<<grid, 256>>>(X, W, out);
}

// round 12
// speedup vs baseline: 2.7223x; 2.7223x over previous
#include <cuda_runtime.h>
#include <cuda_bf16.h>
#include <cstdint>

// out[o, b] = sum_k W[k, o] * X[b, k]
//   M = 2048 (o), N = 8192 (b), K = 2048, fp32 in/out.
// Split-bf16 via augmented K: A' = [Ah | Ah | Al], B' = [Bh | Bl | Bh], K' = 6144.
// One plain bf16 mma.sync GEMM then computes AhBh + AhBl + AlBh in fp32 accums.
// (All PTX here is sm_80-level: cp.async / ldmatrix / mma.sync — no 'a'-suffix
//  instructions, so it assembles for the harness's plain sm_103 target.)
// Bias intentionally NOT added (reference discards it).

#define BATCH_SZ 8192
#define K_DIM    2048
#define M_DIM    2048

constexpr int CTA_M  = 128;
constexpr int CTA_N  = 128;
constexpr int KCH    = 64;                    // k per chunk (64 bf16 = 128B rows)
constexpr int N_MT   = M_DIM / CTA_M;         // 16
constexpr int N_NT   = BATCH_SZ / CTA_N;      // 64
constexpr int KCHUNKS = 3 * (K_DIM / KCH);    // 96 (3 sections x 32)
constexpr int TILE_B = 128 * KCH * 2;         // 16384 B per [128 x 64] bf16 tile
constexpr int NSTAGE = 3;
constexpr int SMEM_TOTAL = NSTAGE * 2 * TILE_B;  // 98304

// Scratch: pre-swizzled, tile-contiguous bf16 tiles.
// g_A: per (mt, j) tile, j in [0,64): j<32 -> Ah chunk j, j>=32 -> Al chunk j-32.
// g_B: per (nt, j) tile, j<32 -> Bh chunk j, j>=32 -> Bl chunk j-32.
__device__ __align__(1024) unsigned char g_A[(size_t)N_MT * 64 * TILE_B]; // 16 MB
__device__ __align__(1024) unsigned char g_B[(size_t)N_NT * 64 * TILE_B]; // 64 MB

// ---------------- helpers ----------------
__device__ __forceinline__ uint32_t smem_u32(const void* p) {
    uint32_t a;
    asm("{ .reg .u64 t; cvta.to.shared.u64 t, %1; cvt.u32.u64 %0, t; }" : "=r"(a) : "l"(p));
    return a;
}
// SW128 swizzle; for 128B rows with col<128 this is off ^ ((row&7)<<4)
__device__ __forceinline__ uint32_t swz128(uint32_t off) {
    return off ^ ((off >> 3) & 0x70);
}
__device__ __forceinline__ void cp16(uint32_t dst, const void* src) {
    asm volatile("cp.async.cg.shared.global [%0], [%1], 16;"
                 :: "r"(dst), "l"(src) : "memory");
}
#define CP_COMMIT() asm volatile("cp.async.commit_group;" ::: "memory")
#define CP_WAIT1()  asm volatile("cp.async.wait_group 1;" ::: "memory")

#define LDSM_X4(r0, r1, r2, r3, addr) \
    asm volatile("ldmatrix.sync.aligned.m8n8.x4.shared.b16 {%0,%1,%2,%3}, [%4];" \
                 : "=r"(r0), "=r"(r1), "=r"(r2), "=r"(r3) : "r"(addr))

#define MMA16816(d, a, b0, b1) \
    asm volatile("mma.sync.aligned.m16n8k16.row.col.f32.bf16.bf16.f32 " \
                 "{%0,%1,%2,%3}, {%4,%5,%6,%7}, {%8,%9}, {%0,%1,%2,%3};" \
                 : "+f"((d)[0]), "+f"((d)[1]), "+f"((d)[2]), "+f"((d)[3]) \
                 : "r"((a)[0]), "r"((a)[1]), "r"((a)[2]), "r"((a)[3]), \
                   "r"(b0), "r"(b1))

__device__ __forceinline__ uint32_t pack2(float x, float y) {
    __nv_bfloat162 h = __floats2bfloat162_rn(x, y);   // x -> low 16 bits
    return *reinterpret_cast<uint32_t*>(&h);
}

// ---------------- convert W: [k, o] fp32 -> A tiles [o=128][k=64] bf16 hi/lo ----------------
__global__ __launch_bounds__(256) void conv_w_kernel(const float* __restrict__ W) {
    __shared__ float s[64][129];                 // [k_local][o_local], padded
    const int mt = blockIdx.x, kc = blockIdx.y;  // (16, 32)
    const int t = threadIdx.x;

    for (int i = t; i < 2048; i += 256) {        // 2048 float4, coalesced along o
        int kl = i >> 5, o4 = (i & 31) * 4;
        float4 v = *(const float4*)(W + (size_t)(kc * 64 + kl) * M_DIM + mt * 128 + o4);
        s[kl][o4 + 0] = v.x; s[kl][o4 + 1] = v.y; s[kl][o4 + 2] = v.z; s[kl][o4 + 3] = v.w;
    }
    __syncthreads();

    const int row = t >> 1;                      // o local 0..127
    const int c0  = (t & 1) * 32;                // k local 0 or 32
    unsigned char* hp = g_A + (size_t)(mt * 64 + kc) * TILE_B;
    unsigned char* lp = g_A + (size_t)(mt * 64 + 32 + kc) * TILE_B;
    #pragma unroll
    for (int j = 0; j < 4; j++) {                // 16B unit = 8 bf16 k-cols
        uint32_t hw[4], lw[4];
        #pragma unroll
        for (int e = 0; e < 4; e++) {
            float v0 = s[c0 + 8 * j + 2 * e + 0][row];
            float v1 = s[c0 + 8 * j + 2 * e + 1][row];
            __nv_bfloat16 h0 = __float2bfloat16(v0);
            __nv_bfloat16 h1 = __float2bfloat16(v1);
            hw[e] = pack2(v0, v1);
            lw[e] = pack2(v0 - __bfloat162float(h0), v1 - __bfloat162float(h1));
        }
        uint32_t so = swz128((uint32_t)(row * 128 + (c0 + 8 * j) * 2));
        *(uint4*)(hp + so) = make_uint4(hw[0], hw[1], hw[2], hw[3]);
        *(uint4*)(lp + so) = make_uint4(lw[0], lw[1], lw[2], lw[3]);
    }
}

// ---------------- convert X: [b, k] fp32 -> B tiles [b=128][k=64] bf16 hi/lo ----------------
__global__ __launch_bounds__(256) void conv_x_kernel(const float* __restrict__ X) {
    const int nt = blockIdx.x, kc = blockIdx.y;  // (64, 32)
    const int t = threadIdx.x;
    const int row = t >> 1;                      // b local 0..127
    const int kh  = (t & 1) * 32;                // k local 0 or 32

    const float* src = X + (size_t)(nt * 128 + row) * K_DIM + kc * 64 + kh;
    unsigned char* hp = g_B + (size_t)(nt * 64 + kc) * TILE_B;
    unsigned char* lp = g_B + (size_t)(nt * 64 + 32 + kc) * TILE_B;

    #pragma unroll
    for (int j2 = 0; j2 < 4; j2++) {             // 8 k per 16B unit
        float4 v0 = *(const float4*)(src + 8 * j2);
        float4 v1 = *(const float4*)(src + 8 * j2 + 4);
        float f[8] = {v0.x, v0.y, v0.z, v0.w, v1.x, v1.y, v1.z, v1.w};
        uint32_t hw[4], lw[4];
        #pragma unroll
        for (int e = 0; e < 4; e++) {
            __nv_bfloat16 h0 = __float2bfloat16(f[2 * e]);
            __nv_bfloat16 h1 = __float2bfloat16(f[2 * e + 1]);
            hw[e] = pack2(f[2 * e], f[2 * e + 1]);
            lw[e] = pack2(f[2 * e] - __bfloat162float(h0),
                          f[2 * e + 1] - __bfloat162float(h1));
        }
        uint32_t so = swz128((uint32_t)(row * 128 + (kh + 8 * j2) * 2));
        *(uint4*)(hp + so) = make_uint4(hw[0], hw[1], hw[2], hw[3]);
        *(uint4*)(lp + so) = make_uint4(lw[0], lw[1], lw[2], lw[3]);
    }
}

// ---------------- GEMM: cp.async + ldmatrix + mma.sync bf16, K' = 6144 ----------------
__global__ __launch_bounds__(256, 2)
void gemm_hmma_kernel(float* __restrict__ out) {
    extern __shared__ unsigned char smem[];
    const uint32_t sb = smem_u32(smem);
    const int t = threadIdx.x;
    const int warp = t >> 5, L = t & 31;
    const int mt = blockIdx.y, nt = blockIdx.x;
    const int wm = warp >> 2, wn = warp & 3;     // warp tile: 64(m) x 32(n)

    const unsigned char* gA = g_A + (size_t)mt * 64 * TILE_B;
    const unsigned char* gB = g_B + (size_t)nt * 64 * TILE_B;

    // Per-lane ldmatrix address components (SW128: addr = row*128 + (col ^ ((row&7)<<4)))
    uint32_t aRow[4], aSwz[4];
    #pragma unroll
    for (int mi = 0; mi < 4; mi++) {
        int r = wm * 64 + mi * 16 + (L & 15);    // lanes 0-15 rows, 16-31 same rows (col+8)
        aRow[mi] = (uint32_t)(r * 128);
        aSwz[mi] = (uint32_t)((r & 7) << 4);
    }
    const uint32_t aCol = (uint32_t)((L >> 4) * 16);
    uint32_t bRow[2], bSwz[2];
    #pragma unroll
    for (int n2 = 0; n2 < 2; n2++) {
        int r = wn * 32 + n2 * 16 + (L & 7) + ((L >> 4) << 3);
        bRow[n2] = (uint32_t)(r * 128);
        bSwz[n2] = (uint32_t)((r & 7) << 4);
    }
    const uint32_t bCol = (uint32_t)(((L >> 3) & 1) * 16);

    float acc[4][4][4];
    #pragma unroll
    for (int mi = 0; mi < 4; mi++)
        #pragma unroll
        for (int ni = 0; ni < 4; ni++)
            #pragma unroll
            for (int e = 0; e < 4; e++) acc[mi][ni][e] = 0.0f;

    // chunk c -> source tile indices (sections: 0:AhBh 1:AhBl 2:AlBh)
    auto issue = [&](int c) {
        const int s = c >> 5, kc = c & 31;
        const unsigned char* aS = gA + (size_t)((s == 2) ? 32 + kc : kc) * TILE_B;
        const unsigned char* bS = gB + (size_t)((s == 1) ? 32 + kc : kc) * TILE_B;
        const uint32_t dst = sb + (uint32_t)(c % NSTAGE) * (2 * TILE_B);
        #pragma unroll
        for (int i = 0; i < 4; i++) {            // 1024 x 16B per tile, 256 threads
            uint32_t off = (uint32_t)(t + i * 256) * 16;
            cp16(dst + off, aS + off);
            cp16(dst + TILE_B + off, bS + off);
        }
    };

    issue(0); CP_COMMIT();
    issue(1); CP_COMMIT();

    for (int c = 0; c < KCHUNKS; c++) {
        CP_WAIT1();                              // chunk c resident
        __syncthreads();                         // also guards slot reuse below
        if (c + 2 < KCHUNKS) issue(c + 2);
        CP_COMMIT();                             // empty group when out of chunks

        const uint32_t As = sb + (uint32_t)(c % NSTAGE) * (2 * TILE_B);
        const uint32_t Bs = As + TILE_B;
        #pragma unroll
        for (int kk = 0; kk < 4; kk++) {         // 4 x k16 per chunk
            const uint32_t ck = (uint32_t)(kk * 32);
            uint32_t a[4][4], b[2][4];
            #pragma unroll
            for (int mi = 0; mi < 4; mi++)
                LDSM_X4(a[mi][0], a[mi][1], a[mi][2], a[mi][3],
                        As + aRow[mi] + ((ck + aCol) ^ aSwz[mi]));
            #pragma unroll
            for (int n2 = 0; n2 < 2; n2++)
                LDSM_X4(b[n2][0], b[n2][1], b[n2][2], b[n2][3],
                        Bs + bRow[n2] + ((ck + bCol) ^ bSwz[n2]));
            #pragma unroll
            for (int mi = 0; mi < 4; mi++)
                #pragma unroll
                for (int ni = 0; ni < 4; ni++)
                    MMA16816(acc[mi][ni], a[mi],
                             b[ni >> 1][(ni & 1) * 2], b[ni >> 1][(ni & 1) * 2 + 1]);
        }
    }

    // Epilogue: d-frag lane mapping: d0,d1 -> (row=L/4, col=2*(L%4)); d2,d3 -> row+8
    const int oB = mt * 128 + wm * 64;
    const int bB = nt * 128 + wn * 32;
    #pragma unroll
    for (int mi = 0; mi < 4; mi++) {
        #pragma unroll
        for (int ni = 0; ni < 4; ni++) {
            const int o = oB + mi * 16 + (L >> 2);
            const int bcol = bB + ni * 8 + (L & 3) * 2;
            *(float2*)&out[(size_t)o * BATCH_SZ + bcol] =
                make_float2(acc[mi][ni][0], acc[mi][ni][1]);
            *(float2*)&out[(size_t)(o + 8) * BATCH_SZ + bcol] =
                make_float2(acc[mi][ni][2], acc[mi][ni][3]);
        }
    }
}

// ---------------- launch ----------------
extern "C" void kernel_launch(void* const* d_in, const int* in_sizes, int n_in,
                              void* d_out, int out_size)
{
    const float* X = (const float*)d_in[0];   // [8192, 2048]
    const float* W = (const float*)d_in[1];   // [2048, 2048]
    float* out = (float*)d_out;               // [2048, 8192]

    cudaFuncSetAttribute(gemm_hmma_kernel,
                         cudaFuncAttributeMaxDynamicSharedMemorySize, SMEM_TOTAL);

    conv_w_kernel<<<dim3(N_MT, 32), 256>>>(W);
    conv_x_kernel<<<dim3(N_NT, 32), 256>>>(X);
    gemm_hmma_kernel<<<dim3(N_NT, N_MT), 256, SMEM_TOTAL>>>(out);
}